// round 5
// baseline (speedup 1.0000x reference)
#include <cuda_runtime.h>
#include <cstdint>

// Row gather: out[row][:] = table[idx[row]][:], row in [0, 212992), row = 128B.
// R4 showed occupancy (57%) was the limiter: 832 blocks = 6656 warps < 9472
// warp slots. This version: 16 rows per warp, 4 float4 gathers per thread,
// 1664 blocks = 13312 warps -> chip fully resident (~1.4 waves).
// Dtype probe (int32 vs int64) is per-warp via __any_sync (no block barrier).

static constexpr int  EMB_DIM        = 32;
static constexpr long NROWS          = 4096L * 26L * 2L;   // 212992
static constexpr int  THREADS        = 256;
static constexpr int  VECS_PER_ROW   = EMB_DIM / 4;        // 8
static constexpr int  ROWS_PER_WARP  = 16;
static constexpr int  ROWS_PER_BLOCK = (THREADS / 32) * ROWS_PER_WARP;  // 128
static constexpr int  BLOCKS         = (int)(NROWS / ROWS_PER_BLOCK);   // 1664, exact

__global__ __launch_bounds__(THREADS)
void gather_rows_kernel(const void*   __restrict__ idx_raw,
                        const float4* __restrict__ table,
                        float4*       __restrict__ out)
{
    const int lane = threadIdx.x & 31;
    const int warp = threadIdx.x >> 5;

    // ---- per-warp dtype probe: high word of first 32 8-byte pairs ----
    // (L2/L1-hot after the first warps; no block-level barrier needed)
    unsigned int hi = ((const unsigned int*)idx_raw)[2 * lane + 1];
    const bool is32 = __any_sync(0xffffffffu, hi != 0);

    const long rowBase = ((long)blockIdx.x * (THREADS / 32) + warp) * ROWS_PER_WARP;

    // ---- coalesced index load: lanes 0..15 carry the 16 row indices ----
    const int  ilane = lane & 15;
    long long  myIdx;
    if (is32) myIdx = (long long)__ldg(((const int*)idx_raw) + rowBase + ilane);
    else      myIdx = __ldg(((const long long*)idx_raw) + rowBase + ilane);

    const int subrow = lane >> 3;   // 0..3
    const int col    = lane & 7;    // float4 slot in row

    // ---- distribute: step s covers rows rowBase + s*4 .. +3 ----
    long r[4];
#pragma unroll
    for (int s = 0; s < 4; s++)
        r[s] = (long)__shfl_sync(0xffffffffu, myIdx, s * 4 + subrow);

    // ---- 4 independent gathers (MLP=4), then 4 coalesced stores ----
    float4 v[4];
#pragma unroll
    for (int s = 0; s < 4; s++)
        v[s] = __ldg(table + r[s] * VECS_PER_ROW + col);

#pragma unroll
    for (int s = 0; s < 4; s++)
        out[(rowBase + s * 4 + subrow) * VECS_PER_ROW + col] = v[s];
}

extern "C" void kernel_launch(void* const* d_in, const int* in_sizes, int n_in,
                              void* d_out, int out_size)
{
    // Pick the index tensor by element count (212992 vs 32,000,000).
    const void*  idx;
    const float* table;
    if (in_sizes[0] == (int)NROWS) {
        idx   = d_in[0];
        table = (const float*)d_in[1];
    } else {
        idx   = d_in[1];
        table = (const float*)d_in[0];
    }

    gather_rows_kernel<<<BLOCKS, THREADS>>>(idx, (const float4*)table, (float4*)d_out);
}

// round 7
// speedup vs baseline: 1.0208x; 1.0208x over previous
#include <cuda_runtime.h>
#include <cstdint>

// Row gather: out[row][:] = table[idx[row]][:], row in [0, 212992), row = 128B.
// 64 rows per warp, 16 independent float4 gathers per thread (MLP=16),
// streaming (__stcs) stores so dead output writes don't evict the table in L2.
//
// R6 bug fixed: lane L now carries rows rowBase+L (i0) and rowBase+32+L (i1),
// so the i0/i1 component is uniform per unrolled step — shuffle source and
// published value always agree.

static constexpr int  EMB_DIM        = 32;
static constexpr long NROWS          = 4096L * 26L * 2L;   // 212992
static constexpr int  THREADS        = 256;
static constexpr int  VECS_PER_ROW   = EMB_DIM / 4;        // 8
static constexpr int  ROWS_PER_WARP  = 64;
static constexpr int  ROWS_PER_BLOCK = (THREADS / 32) * ROWS_PER_WARP;  // 512
static constexpr int  BLOCKS         = (int)(NROWS / ROWS_PER_BLOCK);   // 416, exact
static constexpr int  STEPS          = 16;                 // 4 rows per step

__global__ __launch_bounds__(THREADS)
void gather_rows_kernel(const void*   __restrict__ idx_raw,
                        const float4* __restrict__ table,
                        float4*       __restrict__ out)
{
    const int lane = threadIdx.x & 31;
    const int warp = threadIdx.x >> 5;

    // ---- per-warp dtype probe: high word of first 32 8-byte pairs ----
    unsigned int hiw = ((const unsigned int*)idx_raw)[2 * lane + 1];
    const bool is32 = __any_sync(0xffffffffu, hiw != 0);

    const long rowBase = ((long)blockIdx.x * (THREADS / 32) + warp) * ROWS_PER_WARP;

    // ---- two coalesced index loads: lane carries rows L and L+32 ----
    long long i0, i1;
    if (is32) {
        const int* ip = (const int*)idx_raw + rowBase;
        i0 = __ldg(ip + lane);
        i1 = __ldg(ip + 32 + lane);
    } else {
        const long long* lp = (const long long*)idx_raw + rowBase;
        i0 = __ldg(lp + lane);
        i1 = __ldg(lp + 32 + lane);
    }

    const int subrow = lane >> 3;   // 0..3: row within a 4-row step
    const int col    = lane & 7;    // float4 slot within row

    // ---- distribute: steps 0..7 from i0 (rows 0..31), 8..15 from i1 ----
    long r[STEPS];
#pragma unroll
    for (int s = 0; s < 8; s++)
        r[s] = (long)__shfl_sync(0xffffffffu, i0, s * 4 + subrow);
#pragma unroll
    for (int s = 8; s < STEPS; s++)
        r[s] = (long)__shfl_sync(0xffffffffu, i1, (s - 8) * 4 + subrow);

    // ---- 16 independent gathers (MLP=16) ----
    float4 v[STEPS];
#pragma unroll
    for (int s = 0; s < STEPS; s++)
        v[s] = __ldg(table + r[s] * VECS_PER_ROW + col);

    // ---- 16 coalesced streaming stores (512B contiguous per warp/step) ----
#pragma unroll
    for (int s = 0; s < STEPS; s++)
        __stcs(out + (rowBase + s * 4 + subrow) * VECS_PER_ROW + col, v[s]);
}

extern "C" void kernel_launch(void* const* d_in, const int* in_sizes, int n_in,
                              void* d_out, int out_size)
{
    // Pick the index tensor by element count (212992 vs 32,000,000).
    const void*  idx;
    const float* table;
    if (in_sizes[0] == (int)NROWS) {
        idx   = d_in[0];
        table = (const float*)d_in[1];
    } else {
        idx   = d_in[1];
        table = (const float*)d_in[0];
    }

    gather_rows_kernel<<<BLOCKS, THREADS>>>(idx, (const float4*)table, (float4*)d_out);
}

// round 8
// speedup vs baseline: 1.0239x; 1.0030x over previous
#include <cuda_runtime.h>
#include <cstdint>

// Row gather: out[row][:] = table[idx[row]][:], row in [0, 212992), row = 128B.
// Sweep evidence (R4/R5/R7): optimum at 32 rows/warp, MLP=8.
// This round: 128-thread blocks for finer SM packing (1664 blocks),
// __ldcg gathers (bypass useless L1 allocation on a 26MB random footprint),
// __stcs streaming stores (dead data, don't disturb L2 table residency).

static constexpr int  EMB_DIM        = 32;
static constexpr long NROWS          = 4096L * 26L * 2L;   // 212992
static constexpr int  THREADS        = 128;
static constexpr int  VECS_PER_ROW   = EMB_DIM / 4;        // 8
static constexpr int  ROWS_PER_WARP  = 32;
static constexpr int  WARPS_PER_BLOCK= THREADS / 32;       // 4
static constexpr int  ROWS_PER_BLOCK = WARPS_PER_BLOCK * ROWS_PER_WARP;  // 128
static constexpr int  BLOCKS         = (int)(NROWS / ROWS_PER_BLOCK);    // 1664, exact
static constexpr int  STEPS          = 8;                  // 4 rows per step

__global__ __launch_bounds__(THREADS)
void gather_rows_kernel(const void*   __restrict__ idx_raw,
                        const float4* __restrict__ table,
                        float4*       __restrict__ out)
{
    const int lane = threadIdx.x & 31;
    const int warp = threadIdx.x >> 5;

    // ---- per-warp dtype probe: high word of first 32 8-byte pairs ----
    unsigned int hiw = ((const unsigned int*)idx_raw)[2 * lane + 1];
    const bool is32 = __any_sync(0xffffffffu, hiw != 0);

    const long rowBase = ((long)blockIdx.x * WARPS_PER_BLOCK + warp) * ROWS_PER_WARP;

    // ---- one coalesced index load: lane L carries row rowBase+L ----
    long long myIdx;
    if (is32) myIdx = (long long)__ldg(((const int*)idx_raw) + rowBase + lane);
    else      myIdx = __ldg(((const long long*)idx_raw) + rowBase + lane);

    const int subrow = lane >> 3;   // 0..3: row within a 4-row step
    const int col    = lane & 7;    // float4 slot within row

    // ---- distribute indices: step s covers rows rowBase + s*4 .. +3 ----
    long r[STEPS];
#pragma unroll
    for (int s = 0; s < STEPS; s++)
        r[s] = (long)__shfl_sync(0xffffffffu, myIdx, s * 4 + subrow);

    // ---- 8 independent L2-only gathers (MLP=8, no L1 allocation) ----
    float4 v[STEPS];
#pragma unroll
    for (int s = 0; s < STEPS; s++)
        v[s] = __ldcg(table + r[s] * VECS_PER_ROW + col);

    // ---- 8 coalesced streaming stores (512B contiguous per warp/step) ----
#pragma unroll
    for (int s = 0; s < STEPS; s++)
        __stcs(out + (rowBase + s * 4 + subrow) * VECS_PER_ROW + col, v[s]);
}

extern "C" void kernel_launch(void* const* d_in, const int* in_sizes, int n_in,
                              void* d_out, int out_size)
{
    // Pick the index tensor by element count (212992 vs 32,000,000).
    const void*  idx;
    const float* table;
    if (in_sizes[0] == (int)NROWS) {
        idx   = d_in[0];
        table = (const float*)d_in[1];
    } else {
        idx   = d_in[1];
        table = (const float*)d_in[0];
    }

    gather_rows_kernel<<<BLOCKS, THREADS>>>(idx, (const float4*)table, (float4*)d_out);
}